// round 14
// baseline (speedup 1.0000x reference)
#include <cuda_runtime.h>

// DPLoss: masked per-row MSE of (pred - log(alignment)), normalized by row
// length, then mean over batch.
//
// Inputs (metadata order):
//   d_in[0] = pred            float32 [B, T]
//   d_in[1] = alignment       float32 [B, T]
//   d_in[2] = token_lengths   int32   [B]
// Output: scalar float32.
//
// Design (R12): warp-autonomous streaming. Every prior variant (block-per-
// row, 2D chunks, persistent static, block work-stealing) pinned at ~30%
// DRAM: block-lockstep bursts of ~16KB separated by barrier + ticket-atomic
// + len-load serial chains left loads in flight only ~half the time.
// Now: the work unit is a WARP. No __syncthreads in the hot loop. Warps pull
// row tickets (lane-0 atomic + shfl broadcast) with ONE-AHEAD prefetch of
// both the next ticket and its len, so atomic/len latency hides under the
// current row's streaming. Row body is 4x-unrolled -> 8 LDG.128 outstanding
// per thread. 2960 warps, ~1.4 rows each, dynamically balanced.

#define BLOCK_THREADS 256
#define WARPS_PER_BLOCK (BLOCK_THREADS / 32)
#define GRID_BLOCKS 370          // 2960 warps, ~2.5 blocks/SM
#define NSLOTS 64

__device__ float        g_slots[NSLOTS];   // zero-init at module load
__device__ unsigned int g_counter;         // zero-init at module load
__device__ unsigned int g_ticket;          // zero-init at module load

__device__ __forceinline__ unsigned int warp_ticket(int lane) {
    unsigned int t = 0;
    if (lane == 0) t = atomicAdd(&g_ticket, 1u);
    return __shfl_sync(0xFFFFFFFFu, t, 0);
}

__global__ __launch_bounds__(BLOCK_THREADS) void dploss_warp(
    const float* __restrict__ pred,
    const float* __restrict__ alignment,
    const int*   __restrict__ lens,
    float* __restrict__ out,
    int T, int B, float inv_B, unsigned int nblocks)
{
    const int lane = threadIdx.x & 31;
    const int wid  = threadIdx.x >> 5;

    float acc = 0.0f;   // running, scaled by inv_B/len per row

    // ---- warp-autonomous ticket loop, one-ahead prefetch ----
    unsigned int t = warp_ticket(lane);
    int len = (t < (unsigned int)B) ? __ldg(lens + t) : 0;

    while (t < (unsigned int)B) {
        // Prefetch next ticket + its len; latency overlaps this row's work.
        const unsigned int tn = warp_ticket(lane);
        const int len_n = (tn < (unsigned int)B) ? __ldg(lens + tn) : 0;

        const float4* __restrict__ p4 =
            reinterpret_cast<const float4*>(pred + (size_t)t * T);
        const float4* __restrict__ a4 =
            reinterpret_cast<const float4*>(alignment + (size_t)t * T);

        const int nfull = len >> 2;       // fully-valid float4 vectors
        float cs = 0.0f;

        int v = lane;
        // 4x-unrolled main loop: 8 LDG.128 in flight per thread.
        for (; v + 96 < nfull; v += 128) {
            const float4 pa = p4[v];
            const float4 pb = p4[v + 32];
            const float4 pc = p4[v + 64];
            const float4 pd = p4[v + 96];
            const float4 aa = a4[v];
            const float4 ab = a4[v + 32];
            const float4 ac = a4[v + 64];
            const float4 ad = a4[v + 96];

            float d;
            d = pa.x - __logf(aa.x); cs = fmaf(d, d, cs);
            d = pa.y - __logf(aa.y); cs = fmaf(d, d, cs);
            d = pa.z - __logf(aa.z); cs = fmaf(d, d, cs);
            d = pa.w - __logf(aa.w); cs = fmaf(d, d, cs);
            d = pb.x - __logf(ab.x); cs = fmaf(d, d, cs);
            d = pb.y - __logf(ab.y); cs = fmaf(d, d, cs);
            d = pb.z - __logf(ab.z); cs = fmaf(d, d, cs);
            d = pb.w - __logf(ab.w); cs = fmaf(d, d, cs);
            d = pc.x - __logf(ac.x); cs = fmaf(d, d, cs);
            d = pc.y - __logf(ac.y); cs = fmaf(d, d, cs);
            d = pc.z - __logf(ac.z); cs = fmaf(d, d, cs);
            d = pc.w - __logf(ac.w); cs = fmaf(d, d, cs);
            d = pd.x - __logf(ad.x); cs = fmaf(d, d, cs);
            d = pd.y - __logf(ad.y); cs = fmaf(d, d, cs);
            d = pd.z - __logf(ad.z); cs = fmaf(d, d, cs);
            d = pd.w - __logf(ad.w); cs = fmaf(d, d, cs);
        }
        // remainder full vectors
        for (; v < nfull; v += 32) {
            const float4 p = p4[v];
            const float4 a = a4[v];
            float d;
            d = p.x - __logf(a.x); cs = fmaf(d, d, cs);
            d = p.y - __logf(a.y); cs = fmaf(d, d, cs);
            d = p.z - __logf(a.z); cs = fmaf(d, d, cs);
            d = p.w - __logf(a.w); cs = fmaf(d, d, cs);
        }
        // partial tail vector (0-3 valid elements), lane 0 only
        const int rem = len & 3;
        if (rem && lane == 0) {
            const float4 p = p4[nfull];
            const float4 a = a4[nfull];
            float d = p.x - __logf(a.x); cs = fmaf(d, d, cs);
            if (rem > 1) { d = p.y - __logf(a.y); cs = fmaf(d, d, cs); }
            if (rem > 2) { d = p.z - __logf(a.z); cs = fmaf(d, d, cs); }
        }

        acc = fmaf(cs, inv_B / (float)len, acc);   // exact by linearity
        t = tn; len = len_n;
    }

    // ---- warp reduce + one scatter atomic per warp ----
    #pragma unroll
    for (int off = 16; off > 0; off >>= 1)
        acc += __shfl_xor_sync(0xFFFFFFFFu, acc, off);

    if (lane == 0)
        atomicAdd(&g_slots[(blockIdx.x * WARPS_PER_BLOCK + wid) & (NSLOTS - 1)],
                  acc);

    // ---- last-block finalize (single barrier per block, at the very end) ----
    __syncthreads();

    __shared__ unsigned int s_prev;
    if (threadIdx.x == 0) {
        __threadfence();                       // order slot atomics < arrival
        s_prev = atomicAdd(&g_counter, 1u);
    }
    __syncthreads();

    if (s_prev == nblocks - 1u) {
        __threadfence();                       // acquire slot writes

        float v = (threadIdx.x < NSLOTS) ? g_slots[threadIdx.x] : 0.0f;
        #pragma unroll
        for (int off = 16; off > 0; off >>= 1)
            v += __shfl_xor_sync(0xFFFFFFFFu, v, off);

        __shared__ float ws[2];
        if (wid < 2 && lane == 0) ws[wid] = v;
        __syncthreads();

        if (threadIdx.x == 0) {
            out[0] = ws[0] + ws[1];
            g_counter = 0u;                    // reset for next graph replay
            g_ticket  = 0u;
        }
        if (threadIdx.x < NSLOTS)
            g_slots[threadIdx.x] = 0.0f;
    }
}

extern "C" void kernel_launch(void* const* d_in, const int* in_sizes, int n_in,
                              void* d_out, int out_size)
{
    const float* pred      = (const float*)d_in[0];
    const float* alignment = (const float*)d_in[1];
    const int*   lens      = (const int*)d_in[2];
    float*       out       = (float*)d_out;

    const int B = in_sizes[2];
    const int T = in_sizes[0] / B;

    dploss_warp<<<GRID_BLOCKS, BLOCK_THREADS>>>(
        pred, alignment, lens, out, T, B, 1.0f / (float)B,
        (unsigned int)GRID_BLOCKS);
}